// round 1
// baseline (speedup 1.0000x reference)
#include <cuda_runtime.h>
#include <math.h>

#define NQ 14
#define NSTATE (1 << NQ)
#define NT 512
#define PI_F 3.14159265358979323846f

// ---------------------------------------------------------------------------
// complex helpers (float2 = {re, im})
// ---------------------------------------------------------------------------
__device__ __forceinline__ float2 cmul(float2 a, float2 b) {
    float2 r;
    r.x = a.x * b.x - a.y * b.y;
    r.y = a.x * b.y + a.y * b.x;
    return r;
}

// bank-conflict swizzle: slot = a ^ ((a>>4)&15) ^ ((a>>8)&15)
// bijective (high bits unchanged); spreads high index bits into bank bits 0-3
__device__ __forceinline__ int sw(int a) {
    return a ^ ((a >> 4) & 15) ^ ((a >> 8) & 15);
}

// shared gate tables (static smem, alongside dynamic state array)
__shared__ float2 gU[3][NQ][4];   // fused rotation matrices, layers 1..3 (ent merged)
__shared__ float2 v0[NQ][2];      // per-qubit 2-vector after encoding+layer0 rotations
__shared__ float  red[16][16];    // per-warp reduction partials (15 used)

// U = RZ(rz) @ RY(ry) @ RX(rx)
__device__ __forceinline__ void make_u(float rx, float ry, float rz, float2 U[4]) {
    float cx, sx, cy, sy, cz, sz;
    sincosf(0.5f * rx, &sx, &cx);
    sincosf(0.5f * ry, &sy, &cy);
    sincosf(0.5f * rz, &sz, &cz);
    // M = RY * RX
    float2 M00 = { cy * cx,  sy * sx };
    float2 M01 = {-sy * cx, -cy * sx };
    float2 M10 = { sy * cx, -cy * sx };
    float2 M11 = { cy * cx, -sy * sx };
    float2 p = { cz, -sz };   // e^{-i rz/2}
    float2 q = { cz,  sz };   // e^{+i rz/2}
    U[0] = cmul(p, M00);
    U[1] = cmul(p, M01);
    U[2] = cmul(q, M10);
    U[3] = cmul(q, M11);
}

// ---------------------------------------------------------------------------
// One register-blocked rotation pass.
//  P0..P4 : index-bit positions held locally per thread (32 amps in registers)
//  N0..N4 : index-bit positions driven by lane id
//  W0..W3 : index-bit positions driven by warp id
//  GRAY   : apply previous layer's entangle permutation at load (a = y^(y>>1))
//  GMASK  : which of the 5 local bits receive a gate this pass
// ---------------------------------------------------------------------------
template<int P0, int P1, int P2, int P3, int P4,
         int N0, int N1, int N2, int N3, int N4,
         int W0, int W1, int W2, int W3,
         bool GRAY, unsigned GMASK>
__device__ __forceinline__ void rot_pass(float2* st, const float2 (*g)[4],
                                         int lane, int warp) {
    const int base =
        (( lane       & 1) << N0) | (((lane >> 1) & 1) << N1) |
        (((lane >> 2) & 1) << N2) | (((lane >> 3) & 1) << N3) |
        (((lane >> 4) & 1) << N4) |
        (( warp       & 1) << W0) | (((warp >> 1) & 1) << W1) |
        (((warp >> 2) & 1) << W2) | (((warp >> 3) & 1) << W3);

    float2 c[32];
#pragma unroll
    for (int j = 0; j < 32; j++) {
        int y = base |
                (( j       & 1) << P0) | (((j >> 1) & 1) << P1) |
                (((j >> 2) & 1) << P2) | (((j >> 3) & 1) << P3) |
                (((j >> 4) & 1) << P4);
        int a = GRAY ? (y ^ (y >> 1)) : y;
        c[j] = st[sw(a)];
    }
    if (GRAY) __syncthreads();  // permuted in-place: all loads before any store

#pragma unroll
    for (int k = 0; k < 5; k++) {
        if (!((GMASK >> k) & 1)) continue;
        const int pos = (k == 0) ? P0 : (k == 1) ? P1 : (k == 2) ? P2
                                      : (k == 3) ? P3 : P4;
        const int q = 13 - pos;  // qubit index (qubit 0 = MSB of state index)
        const float2 u00 = g[q][0], u01 = g[q][1];
        const float2 u10 = g[q][2], u11 = g[q][3];
#pragma unroll
        for (int j = 0; j < 32; j++) {
            if (j & (1 << k)) continue;
            const int j1 = j | (1 << k);
            float2 a0 = c[j], a1 = c[j1];
            float2 n0, n1;
            n0.x = u00.x * a0.x - u00.y * a0.y + u01.x * a1.x - u01.y * a1.y;
            n0.y = u00.x * a0.y + u00.y * a0.x + u01.x * a1.y + u01.y * a1.x;
            n1.x = u10.x * a0.x - u10.y * a0.y + u11.x * a1.x - u11.y * a1.y;
            n1.y = u10.x * a0.y + u10.y * a0.x + u11.x * a1.y + u11.y * a1.x;
            c[j]  = n0;
            c[j1] = n1;
        }
    }

#pragma unroll
    for (int j = 0; j < 32; j++) {
        int y = base |
                (( j       & 1) << P0) | (((j >> 1) & 1) << P1) |
                (((j >> 2) & 1) << P2) | (((j >> 3) & 1) << P3) |
                (((j >> 4) & 1) << P4);
        st[sw(y)] = c[j];
    }
    __syncthreads();
}

// ---------------------------------------------------------------------------
__global__ void __launch_bounds__(NT, 1)
qc_kernel(const float* __restrict__ x,
          const float* __restrict__ prx,
          const float* __restrict__ pry,
          const float* __restrict__ prz,
          const float* __restrict__ pent,
          float* __restrict__ out) {
    extern __shared__ float2 st[];  // 16384 complex amps, swizzled layout

    const int b    = blockIdx.x;
    const int tid  = threadIdx.x;
    const int lane = tid & 31;
    const int warp = tid >> 5;

    // ---- setup: fused gate matrices for layers 1..3 (ent phases merged) ----
    if (tid < 42) {
        const int t = tid / NQ;       // table index 0..2 -> circuit layer t+1
        const int i = tid % NQ;       // qubit
        const int l = t + 1;
        float2 U[4];
        make_u(prx[l * NQ + i], pry[l * NQ + i], prz[l * NQ + i], U);
        if (i > 0) {
            // merge RZ(ent) from previous layer's entangle (acts on permuted bit)
            float ce, se;
            sincosf(0.5f * pent[t * (NQ - 1) + (i - 1)], &se, &ce);
            float2 pe = { ce, -se };
            float2 qe = { ce,  se };
            U[0] = cmul(U[0], pe);  // column 0 *= e^{-ie/2}
            U[2] = cmul(U[2], pe);
            U[1] = cmul(U[1], qe);  // column 1 *= e^{+ie/2}
            U[3] = cmul(U[3], qe);
        }
        gU[t][i][0] = U[0]; gU[t][i][1] = U[1];
        gU[t][i][2] = U[2]; gU[t][i][3] = U[3];
    }
    // ---- setup: per-sample product-state vectors (encoding RY + layer0) ----
    if (tid >= 64 && tid < 64 + NQ) {
        const int i = tid - 64;
        float2 U[4];
        make_u(prx[i], pry[i], prz[i], U);
        const float enc = tanhf(x[b * NQ + i]) * PI_F;
        float ce, se;
        sincosf(0.5f * enc, &se, &ce);  // RY(enc)|0> = (ce, se)
        float2 a, c2;
        a.x  = U[0].x * ce + U[1].x * se;
        a.y  = U[0].y * ce + U[1].y * se;
        c2.x = U[2].x * ce + U[3].x * se;
        c2.y = U[2].y * ce + U[3].y * se;
        v0[i][0] = a;
        v0[i][1] = c2;
    }
    __syncthreads();

    // ---- init pass: write product state directly (state after layer 0) ----
    {
        // index = (j<<9) | tid ; bit b of index <-> qubit 13-b
        float2 h = v0[13][tid & 1];
#pragma unroll
        for (int bp = 1; bp < 9; bp++)
            h = cmul(h, v0[13 - bp][(tid >> bp) & 1]);
#pragma unroll
        for (int j = 0; j < 32; j++) {
            float2 a = h;
#pragma unroll
            for (int k = 0; k < 5; k++)
                a = cmul(a, v0[4 - k][(j >> k) & 1]);
            st[sw((j << 9) | tid)] = a;
        }
    }
    __syncthreads();

    // ---- layers 1..3: each = gray-load pass + 2 identity passes ----------
#pragma unroll 1
    for (int t = 0; t < 3; t++) {
        const float2 (*g)[4] = gU[t];
        // pass A: gates on bits {0,6,7,8,9}; gray load = previous entangle
        rot_pass<0, 6, 7, 8, 9,   1, 2, 3, 4, 5,   10, 11, 12, 13,
                 true, 0x1Fu>(st, g, lane, warp);
        // pass B: gates on bits {1,2,3,4,5}
        rot_pass<1, 2, 3, 4, 5,   0, 6, 7, 8, 9,   10, 11, 12, 13,
                 false, 0x1Fu>(st, g, lane, warp);
        // pass C: gates on bits {10,11,12,13} (bit 0 local but already done)
        rot_pass<0, 10, 11, 12, 13,   1, 2, 3, 4, 5,   6, 7, 8, 9,
                 false, 0x1Eu>(st, g, lane, warp);
    }

    // ---- measurement: final entangle is pure bit-permutation + phases ----
    // |amp|^2 invariant under phases; final index y = suffix-XOR of stored z.
    float tsum = 0.f;
    float s[NQ];
#pragma unroll
    for (int q = 0; q < NQ; q++) s[q] = 0.f;

#pragma unroll
    for (int j = 0; j < 32; j++) {
        const int z = (j << 9) | tid;
        const float2 a = st[sw(z)];
        const float p = a.x * a.x + a.y * a.y;
        int y = z;
        y ^= y >> 1; y ^= y >> 2; y ^= y >> 4; y ^= y >> 8;
        tsum += p;
#pragma unroll
        for (int q = 0; q < NQ; q++)
            if ((y >> (13 - q)) & 1) s[q] += p;
    }

    // warp reduce 15 values
#pragma unroll
    for (int o = 16; o; o >>= 1) {
        tsum += __shfl_xor_sync(0xFFFFFFFFu, tsum, o);
#pragma unroll
        for (int q = 0; q < NQ; q++)
            s[q] += __shfl_xor_sync(0xFFFFFFFFu, s[q], o);
    }
    if (lane == 0) {
        red[warp][0] = tsum;
#pragma unroll
        for (int q = 0; q < NQ; q++) red[warp][1 + q] = s[q];
    }
    __syncthreads();

    if (tid < NQ) {
        float tt = 0.f, ss = 0.f;
#pragma unroll
        for (int w = 0; w < 16; w++) {
            tt += red[w][0];
            ss += red[w][1 + tid];
        }
        // <Z_q> = P(bit=0) - P(bit=1) = total - 2 * P(bit=1)
        out[b * NQ + tid] = tt - 2.f * ss;
    }
}

// ---------------------------------------------------------------------------
extern "C" void kernel_launch(void* const* d_in, const int* in_sizes, int n_in,
                              void* d_out, int out_size) {
    const float* x    = (const float*)d_in[0];  // (128, 14)
    const float* prx  = (const float*)d_in[1];  // (4, 14)
    const float* pry  = (const float*)d_in[2];  // (4, 14)
    const float* prz  = (const float*)d_in[3];  // (4, 14)
    const float* pent = (const float*)d_in[4];  // (4, 13)
    float* out = (float*)d_out;                 // (128, 14)

    const int B = in_sizes[0] / NQ;
    const size_t smem = NSTATE * sizeof(float2);  // 131072 bytes

    cudaFuncSetAttribute(qc_kernel,
                         cudaFuncAttributeMaxDynamicSharedMemorySize,
                         (int)smem);
    qc_kernel<<<B, NT, smem>>>(x, prx, pry, prz, pent, out);
}

// round 2
// speedup vs baseline: 1.2461x; 1.2461x over previous
#include <cuda_runtime.h>
#include <math.h>

#define NQ 14
#define NSTATE (1 << NQ)
#define NT 512
#define PI_F 3.14159265358979323846f

typedef unsigned long long u64;

// ---------------------------------------------------------------------------
// packed f32x2 helpers
// ---------------------------------------------------------------------------
__device__ __forceinline__ u64 pk(float a, float b) {
    u64 r; asm("mov.b64 %0,{%1,%2};" : "=l"(r) : "f"(a), "f"(b)); return r;
}
__device__ __forceinline__ void unpk(u64 v, float& a, float& b) {
    asm("mov.b64 {%0,%1},%2;" : "=f"(a), "=f"(b) : "l"(v));
}
__device__ __forceinline__ u64 fma2(u64 a, u64 b, u64 c) {
    u64 d; asm("fma.rn.f32x2 %0,%1,%2,%3;" : "=l"(d) : "l"(a), "l"(b), "l"(c)); return d;
}
__device__ __forceinline__ u64 mul2(u64 a, u64 b) {
    u64 d; asm("mul.rn.f32x2 %0,%1,%2;" : "=l"(d) : "l"(a), "l"(b)); return d;
}

__device__ __forceinline__ float2 cmul(float2 a, float2 b) {
    float2 r;
    r.x = a.x * b.x - a.y * b.y;
    r.y = a.x * b.y + a.y * b.x;
    return r;
}

// bank swizzle: b0=a0^a5^a9, b1=a1^a6, b2=a2^a7, b3=a3^a8, b4=a4^a9
// bijective lane->bank for every access pattern used below.
__host__ __device__ constexpr int slotf(int a) {
    return a ^ ((a >> 5) & 31) ^ ((a >> 9) & 1);
}
// suffix-xor (inverse of y -> y^(y>>1)); linear over GF(2)
__host__ __device__ constexpr int sxf(int a) {
    a ^= a >> 1; a ^= a >> 2; a ^= a >> 4; a ^= a >> 8;
    return a;
}

// shared tables
__shared__ float2 gT[3][NQ][12];  // packed splat coeffs per (layer-table, qubit)
__shared__ float2 v0[NQ][2];      // per-qubit vector after encoding + layer0
__shared__ float  red[16][16];

__device__ __forceinline__ u64 ld8(const float2* p) {
    return *reinterpret_cast<const u64*>(p);
}

// U = RZ(rz) @ RY(ry) @ RX(rx)
__device__ __forceinline__ void make_u(float rx, float ry, float rz, float2 U[4]) {
    float cx, sx, cy, sy, cz, sz;
    sincosf(0.5f * rx, &sx, &cx);
    sincosf(0.5f * ry, &sy, &cy);
    sincosf(0.5f * rz, &sz, &cz);
    float2 M00 = { cy * cx,  sy * sx };
    float2 M01 = {-sy * cx, -cy * sx };
    float2 M10 = { sy * cx, -cy * sx };
    float2 M11 = { cy * cx, -sy * sx };
    float2 p = { cz, -sz };
    float2 q = { cz,  sz };
    U[0] = cmul(p, M00);
    U[1] = cmul(p, M01);
    U[2] = cmul(q, M10);
    U[3] = cmul(q, M11);
}

// packed butterfly: n0 = u00*a0 + u01*a1 ; n1 = u10*a0 + u11*a1  (two j's per lane)
__device__ __forceinline__ void bfly(u64& a0r, u64& a0i, u64& a1r, u64& a1i,
                                     u64 X00, u64 Y00, u64 M00,
                                     u64 X01, u64 Y01, u64 M01,
                                     u64 X10, u64 Y10, u64 M10,
                                     u64 X11, u64 Y11, u64 M11) {
    u64 n0r = fma2(M01, a1i, fma2(X01, a1r, fma2(M00, a0i, mul2(X00, a0r))));
    u64 n0i = fma2(X01, a1i, fma2(Y01, a1r, fma2(X00, a0i, mul2(Y00, a0r))));
    u64 n1r = fma2(M11, a1i, fma2(X11, a1r, fma2(M10, a0i, mul2(X10, a0r))));
    u64 n1i = fma2(X11, a1i, fma2(Y11, a1r, fma2(X10, a0i, mul2(Y10, a0r))));
    a0r = n0r; a0i = n0i; a1r = n1r; a1i = n1i;
}

// ---------------------------------------------------------------------------
// One fully-packed pass. P0..P3: gated-capable local bits (jj), P4: pack bit
// (never gated). N: lane bits, W: warp bits. GMASK over k=0..3. PERM: store
// with suffix-xor permutation (applies the entangle CNOT-chain).
// ---------------------------------------------------------------------------
template<int P0, int P1, int P2, int P3, int P4,
         int N0, int N1, int N2, int N3, int N4,
         int W0, int W1, int W2, int W3,
         unsigned GMASK, bool PERM>
__device__ __forceinline__ void pass(float* sre, float* sim,
                                     const float2 (*g)[12], int lane, int warp) {
    const int base =
        (( lane       & 1) << N0) | (((lane >> 1) & 1) << N1) |
        (((lane >> 2) & 1) << N2) | (((lane >> 3) & 1) << N3) |
        (((lane >> 4) & 1) << N4) |
        (( warp       & 1) << W0) | (((warp >> 1) & 1) << W1) |
        (((warp >> 2) & 1) << W2) | (((warp >> 3) & 1) << W3);
    const int sb = slotf(base);

    u64 cr[16], ci[16];
#pragma unroll
    for (int jj = 0; jj < 16; jj++) {
        const int K0 = ((jj & 1) << P0) | (((jj >> 1) & 1) << P1) |
                       (((jj >> 2) & 1) << P2) | (((jj >> 3) & 1) << P3);
        const int K1 = K0 | (1 << P4);
        cr[jj] = pk(sre[sb ^ slotf(K0)], sre[sb ^ slotf(K1)]);
        ci[jj] = pk(sim[sb ^ slotf(K0)], sim[sb ^ slotf(K1)]);
    }

#pragma unroll
    for (int k = 0; k < 4; k++) {
        if (!((GMASK >> k) & 1)) continue;
        const int pos = (k == 0) ? P0 : (k == 1) ? P1 : (k == 2) ? P2 : P3;
        const int q = 13 - pos;
        const u64 X00 = ld8(&g[q][0]),  Y00 = ld8(&g[q][1]),  M00 = ld8(&g[q][2]);
        const u64 X01 = ld8(&g[q][3]),  Y01 = ld8(&g[q][4]),  M01 = ld8(&g[q][5]);
        const u64 X10 = ld8(&g[q][6]),  Y10 = ld8(&g[q][7]),  M10 = ld8(&g[q][8]);
        const u64 X11 = ld8(&g[q][9]),  Y11 = ld8(&g[q][10]), M11 = ld8(&g[q][11]);
#pragma unroll
        for (int jj = 0; jj < 16; jj++) {
            if (jj & (1 << k)) continue;
            const int j2 = jj | (1 << k);
            bfly(cr[jj], ci[jj], cr[j2], ci[j2],
                 X00, Y00, M00, X01, Y01, M01, X10, Y10, M10, X11, Y11, M11);
        }
    }

    if (PERM) __syncthreads();  // permuted in-place store: all loads done first
    const int sb2 = PERM ? slotf(sxf(base)) : sb;
#pragma unroll
    for (int jj = 0; jj < 16; jj++) {
        const int K0 = ((jj & 1) << P0) | (((jj >> 1) & 1) << P1) |
                       (((jj >> 2) & 1) << P2) | (((jj >> 3) & 1) << P3);
        const int K1 = K0 | (1 << P4);
        const int C0 = PERM ? slotf(sxf(K0)) : slotf(K0);
        const int C1 = PERM ? slotf(sxf(K1)) : slotf(K1);
        float r0, r1, i0, i1;
        unpk(cr[jj], r0, r1);
        unpk(ci[jj], i0, i1);
        sre[sb2 ^ C0] = r0; sre[sb2 ^ C1] = r1;
        sim[sb2 ^ C0] = i0; sim[sb2 ^ C1] = i1;
    }
    __syncthreads();
}

// ---------------------------------------------------------------------------
__global__ void __launch_bounds__(NT, 1)
qc_kernel(const float* __restrict__ x,
          const float* __restrict__ prx,
          const float* __restrict__ pry,
          const float* __restrict__ prz,
          const float* __restrict__ pent,
          float* __restrict__ out) {
    extern __shared__ float smem[];
    float* sre = smem;            // 16384 floats
    float* sim = smem + NSTATE;   // 16384 floats

    const int b    = blockIdx.x;
    const int tid  = threadIdx.x;
    const int lane = tid & 31;
    const int warp = tid >> 5;

    // ---- setup: packed splat coefficient tables, layers 1..3 (ent merged) --
    if (tid < 42) {
        const int t = tid / NQ;
        const int i = tid % NQ;
        const int l = t + 1;
        float2 U[4];
        make_u(prx[l * NQ + i], pry[l * NQ + i], prz[l * NQ + i], U);
        if (i > 0) {
            float ce, se;
            sincosf(0.5f * pent[t * (NQ - 1) + (i - 1)], &se, &ce);
            float2 pe = { ce, -se };
            float2 qe = { ce,  se };
            U[0] = cmul(U[0], pe);
            U[2] = cmul(U[2], pe);
            U[1] = cmul(U[1], qe);
            U[3] = cmul(U[3], qe);
        }
#pragma unroll
        for (int r = 0; r < 4; r++) {
            gT[t][i][r * 3 + 0] = make_float2( U[r].x,  U[r].x);
            gT[t][i][r * 3 + 1] = make_float2( U[r].y,  U[r].y);
            gT[t][i][r * 3 + 2] = make_float2(-U[r].y, -U[r].y);
        }
    }
    // ---- setup: per-sample product vectors (encoding RY + layer0) ----------
    if (tid >= 64 && tid < 64 + NQ) {
        const int i = tid - 64;
        float2 U[4];
        make_u(prx[i], pry[i], prz[i], U);
        const float enc = tanhf(x[b * NQ + i]) * PI_F;
        float ce, se;
        sincosf(0.5f * enc, &se, &ce);
        float2 a, c2;
        a.x  = U[0].x * ce + U[1].x * se;
        a.y  = U[0].y * ce + U[1].y * se;
        c2.x = U[2].x * ce + U[3].x * se;
        c2.y = U[2].y * ce + U[3].y * se;
        v0[i][0] = a;
        v0[i][1] = c2;
    }
    __syncthreads();

    // ---- init: write product state with layer-0 entangle permutation -------
    // new index w holds old[gray(w)]; z = gray(w) = w ^ (w>>1).
    {
        const int st0 = slotf(tid);
        // z bits 0..7 depend only on tid
        float2 f = v0[13][(tid ^ (tid >> 1)) & 1];
#pragma unroll
        for (int i2 = 1; i2 < 8; i2++)
            f = cmul(f, v0[13 - i2][((tid >> i2) ^ (tid >> (i2 + 1))) & 1]);
        const int t8 = (tid >> 8) & 1;
        float2 h9[2];
        h9[0] = cmul(f, v0[5][t8]);      // z8 = t8 ^ j0, j0 = 0
        h9[1] = cmul(f, v0[5][t8 ^ 1]);  // j0 = 1
#pragma unroll
        for (int j = 0; j < 32; j++) {
            const int jg = (j ^ (j >> 1)) & 31;  // z bits 9..13
            float2 v = h9[j & 1];
            v = cmul(v, v0[4][ jg       & 1]);
            v = cmul(v, v0[3][(jg >> 1) & 1]);
            v = cmul(v, v0[2][(jg >> 2) & 1]);
            v = cmul(v, v0[1][(jg >> 3) & 1]);
            v = cmul(v, v0[0][(jg >> 4) & 1]);
            const int addr = st0 ^ slotf(j << 9);
            sre[addr] = v.x;
            sim[addr] = v.y;
        }
    }
    __syncthreads();

    // ---- layers 1..3: 4 fully-packed passes each ---------------------------
#pragma unroll 1
    for (int t = 0; t < 3; t++) {
        const float2 (*g)[12] = gT[t];
        // pass A: gates positions {6,7,8,9} (qubits 7,6,5,4), pack bit 0
        pass<6, 7, 8, 9, 0,   1, 2, 3, 4, 5,   10, 11, 12, 13,
             0xFu, false>(sre, sim, g, lane, warp);
        // pass B: gates positions {1,2,3,4} (qubits 12,11,10,9), pack bit 5
        pass<1, 2, 3, 4, 5,   0, 6, 7, 8, 9,   10, 11, 12, 13,
             0xFu, false>(sre, sim, g, lane, warp);
        // pass D: gates positions {0,5} (qubits 13,8), pack bit 6
        pass<0, 5, 7, 8, 6,   1, 2, 3, 4, 9,   10, 11, 12, 13,
             0x3u, false>(sre, sim, g, lane, warp);
        // pass C: gates positions {10,11,12,13} (qubits 3,2,1,0), pack bit 0,
        //         then entangle CNOT-chain applied as permuted store
        pass<10, 11, 12, 13, 0,   1, 2, 3, 4, 5,   6, 7, 8, 9,
             0xFu, true>(sre, sim, g, lane, warp);
    }

    // ---- measurement: state already in final (post-entangle) indexing ------
    float tsum = 0.f;
    float sq[5] = {0.f, 0.f, 0.f, 0.f, 0.f};  // qubits 0..4 (w bits 13..9 = j bits)
    {
        const int st0 = slotf(tid);
#pragma unroll
        for (int j = 0; j < 32; j++) {
            const int addr = st0 ^ slotf(j << 9);
            const float re = sre[addr];
            const float im = sim[addr];
            const float p = re * re + im * im;
            tsum += p;
            if (j & 1)  sq[4] += p;  // w bit 9  -> qubit 4
            if (j & 2)  sq[3] += p;
            if (j & 4)  sq[2] += p;
            if (j & 8)  sq[1] += p;
            if (j & 16) sq[0] += p;  // w bit 13 -> qubit 0
        }
    }
    float s[NQ];
#pragma unroll
    for (int q = 0; q < 5; q++) s[q] = sq[q];
#pragma unroll
    for (int q = 5; q < NQ; q++)
        s[q] = ((tid >> (13 - q)) & 1) ? tsum : 0.f;

#pragma unroll
    for (int o = 16; o; o >>= 1) {
        tsum += __shfl_xor_sync(0xFFFFFFFFu, tsum, o);
#pragma unroll
        for (int q = 0; q < NQ; q++)
            s[q] += __shfl_xor_sync(0xFFFFFFFFu, s[q], o);
    }
    if (lane == 0) {
        red[warp][0] = tsum;
#pragma unroll
        for (int q = 0; q < NQ; q++) red[warp][1 + q] = s[q];
    }
    __syncthreads();

    if (tid < NQ) {
        float tt = 0.f, ss = 0.f;
#pragma unroll
        for (int w = 0; w < 16; w++) {
            tt += red[w][0];
            ss += red[w][1 + tid];
        }
        out[b * NQ + tid] = tt - 2.f * ss;
    }
}

// ---------------------------------------------------------------------------
extern "C" void kernel_launch(void* const* d_in, const int* in_sizes, int n_in,
                              void* d_out, int out_size) {
    const float* x    = (const float*)d_in[0];
    const float* prx  = (const float*)d_in[1];
    const float* pry  = (const float*)d_in[2];
    const float* prz  = (const float*)d_in[3];
    const float* pent = (const float*)d_in[4];
    float* out = (float*)d_out;

    const int B = in_sizes[0] / NQ;
    const size_t smem = 2 * NSTATE * sizeof(float);  // 131072 bytes SoA

    cudaFuncSetAttribute(qc_kernel,
                         cudaFuncAttributeMaxDynamicSharedMemorySize,
                         (int)smem);
    qc_kernel<<<B, NT, smem>>>(x, prx, pry, prz, pent, out);
}

// round 3
// speedup vs baseline: 1.3130x; 1.0537x over previous
#include <cuda_runtime.h>
#include <math.h>

#define NQ 14
#define NSTATE (1 << NQ)
#define NT 512
#define PI_F 3.14159265358979323846f

typedef unsigned long long u64;

// ---------------------------------------------------------------------------
// packed f32x2 helpers
// ---------------------------------------------------------------------------
__device__ __forceinline__ u64 pk(float a, float b) {
    u64 r; asm("mov.b64 %0,{%1,%2};" : "=l"(r) : "f"(a), "f"(b)); return r;
}
__device__ __forceinline__ void unpk(u64 v, float& a, float& b) {
    asm("mov.b64 {%0,%1},%2;" : "=f"(a), "=f"(b) : "l"(v));
}
__device__ __forceinline__ u64 fma2(u64 a, u64 b, u64 c) {
    u64 d; asm("fma.rn.f32x2 %0,%1,%2,%3;" : "=l"(d) : "l"(a), "l"(b), "l"(c)); return d;
}
__device__ __forceinline__ u64 mul2(u64 a, u64 b) {
    u64 d; asm("mul.rn.f32x2 %0,%1,%2;" : "=l"(d) : "l"(a), "l"(b)); return d;
}
__device__ __forceinline__ u64 add2(u64 a, u64 b) {
    u64 d; asm("add.rn.f32x2 %0,%1,%2;" : "=l"(d) : "l"(a), "l"(b)); return d;
}

__device__ __forceinline__ float2 cmul(float2 a, float2 b) {
    float2 r;
    r.x = a.x * b.x - a.y * b.y;
    r.y = a.x * b.y + a.y * b.x;
    return r;
}

// swizzle: slot bits1-4 ^= bits5-8; bit0 = a0 ONLY (=> clean 64-bit pairing)
__host__ __device__ constexpr int slotf(int a) {
    return a ^ (((a >> 5) & 15) << 1);
}
// suffix-xor (inverse of y -> y^(y>>1)), XOR-linear
__host__ __device__ constexpr int sxf(int a) {
    a ^= a >> 1; a ^= a >> 2; a ^= a >> 4; a ^= a >> 8;
    return a;
}
__host__ __device__ constexpr int parc(int a) {  // parity, constexpr
    a ^= a >> 8; a ^= a >> 4; a ^= a >> 2; a ^= a >> 1;
    return a & 1;
}

// shared tables
__shared__ float2 gT[3][NQ][12];  // splat coeffs; [13] uses special 6-entry layout
__shared__ float2 v0[NQ][2];      // per-qubit vector after encoding + layer0
__shared__ float  red[16][16];

__device__ __forceinline__ u64 ld8(const float2* p) {
    return *reinterpret_cast<const u64*>(p);
}

// U = RZ(rz) @ RY(ry) @ RX(rx)
__device__ __forceinline__ void make_u(float rx, float ry, float rz, float2 U[4]) {
    float cx, sx, cy, sy, cz, sz;
    sincosf(0.5f * rx, &sx, &cx);
    sincosf(0.5f * ry, &sy, &cy);
    sincosf(0.5f * rz, &sz, &cz);
    float2 M00 = { cy * cx,  sy * sx };
    float2 M01 = {-sy * cx, -cy * sx };
    float2 M10 = { sy * cx, -cy * sx };
    float2 M11 = { cy * cx, -sy * sx };
    float2 p = { cz, -sz };
    float2 q = { cz,  sz };
    U[0] = cmul(p, M00);
    U[1] = cmul(p, M01);
    U[2] = cmul(q, M10);
    U[3] = cmul(q, M11);
}

// packed butterfly over two registers (two j's per lane, splat coefficients)
__device__ __forceinline__ void bfly(u64& a0r, u64& a0i, u64& a1r, u64& a1i,
                                     u64 X00, u64 Y00, u64 M00,
                                     u64 X01, u64 Y01, u64 M01,
                                     u64 X10, u64 Y10, u64 M10,
                                     u64 X11, u64 Y11, u64 M11) {
    u64 n0r = fma2(M01, a1i, fma2(X01, a1r, fma2(M00, a0i, mul2(X00, a0r))));
    u64 n0i = fma2(X01, a1i, fma2(Y01, a1r, fma2(X00, a0i, mul2(Y00, a0r))));
    u64 n1r = fma2(M11, a1i, fma2(X11, a1r, fma2(M10, a0i, mul2(X10, a0r))));
    u64 n1i = fma2(X11, a1i, fma2(Y11, a1r, fma2(X10, a0i, mul2(Y10, a0r))));
    a0r = n0r; a0i = n0i; a1r = n1r; a1i = n1i;
}

// ---------------------------------------------------------------------------
// One pass. Pack bit is ALWAYS index-bit 0 (slot LSB). P0..P3: jj gate bits.
// N: lane bits, W: warp bits. REGGATE: gate qubit 13 in-register.
// SHFLGATE: gate qubit 8 via shfl (requires N0 == 5). PERM: suffix-xor store.
// ---------------------------------------------------------------------------
template<int P0, int P1, int P2, int P3,
         int N0, int N1, int N2, int N3, int N4,
         int W0, int W1, int W2, int W3,
         bool REGGATE, bool SHFLGATE, bool PERM>
__device__ __forceinline__ void pass(float* sre, float* sim,
                                     const float2 (*g)[12], int lane, int warp) {
    const int base =
        (( lane       & 1) << N0) | (((lane >> 1) & 1) << N1) |
        (((lane >> 2) & 1) << N2) | (((lane >> 3) & 1) << N3) |
        (((lane >> 4) & 1) << N4) |
        (( warp       & 1) << W0) | (((warp >> 1) & 1) << W1) |
        (((warp >> 2) & 1) << W2) | (((warp >> 3) & 1) << W3);
    const int sb = slotf(base);   // bit0 == 0

    u64 cr[16], ci[16];
#pragma unroll
    for (int jj = 0; jj < 16; jj++) {
        const int K = ((jj & 1) << P0) | (((jj >> 1) & 1) << P1) |
                      (((jj >> 2) & 1) << P2) | (((jj >> 3) & 1) << P3);
        const int a = sb ^ slotf(K);
        cr[jj] = *reinterpret_cast<const u64*>(&sre[a]);
        ci[jj] = *reinterpret_cast<const u64*>(&sim[a]);
    }

    // --- 4 jj-bit gates ---
#pragma unroll
    for (int k = 0; k < 4; k++) {
        const int pos = (k == 0) ? P0 : (k == 1) ? P1 : (k == 2) ? P2 : P3;
        const int q = 13 - pos;
        const u64 X00 = ld8(&g[q][0]),  Y00 = ld8(&g[q][1]),  M00 = ld8(&g[q][2]);
        const u64 X01 = ld8(&g[q][3]),  Y01 = ld8(&g[q][4]),  M01 = ld8(&g[q][5]);
        const u64 X10 = ld8(&g[q][6]),  Y10 = ld8(&g[q][7]),  M10 = ld8(&g[q][8]);
        const u64 X11 = ld8(&g[q][9]),  Y11 = ld8(&g[q][10]), M11 = ld8(&g[q][11]);
#pragma unroll
        for (int jj = 0; jj < 16; jj++) {
            if (jj & (1 << k)) continue;
            const int j2 = jj | (1 << k);
            bfly(cr[jj], ci[jj], cr[j2], ci[j2],
                 X00, Y00, M00, X01, Y01, M01, X10, Y10, M10, X11, Y11, M11);
        }
    }

    // --- in-register gate on the pack bit (qubit 13) ---
    if (REGGATE) {
        const u64 A  = ld8(&g[13][0]), B  = ld8(&g[13][1]);
        const u64 E  = ld8(&g[13][2]), F  = ld8(&g[13][3]);
        const u64 Cm = ld8(&g[13][4]), Dm = ld8(&g[13][5]);
#pragma unroll
        for (int jj = 0; jj < 16; jj++) {
            float r0, r1, i0, i1;
            unpk(cr[jj], r0, r1);
            unpk(ci[jj], i0, i1);
            const u64 sar = pk(r1, r0), sai = pk(i1, i0);
            const u64 nr = fma2(Dm, sai, fma2(Cm, ci[jj], fma2(B, sar, mul2(A, cr[jj]))));
            const u64 ni = fma2(B,  sai, fma2(A,  ci[jj], fma2(F, sar, mul2(E, cr[jj]))));
            cr[jj] = nr; ci[jj] = ni;
        }
    }

    // --- shuffle gate on lane bit 0 (index bit 5 => qubit 8) ---
    if (SHFLGATE) {
        const bool odd = lane & 1;
        const u64 Gr = odd ? ld8(&g[8][9])  : ld8(&g[8][0]);
        const u64 Gi = odd ? ld8(&g[8][10]) : ld8(&g[8][1]);
        const u64 Gm = odd ? ld8(&g[8][11]) : ld8(&g[8][2]);
        const u64 Hr = odd ? ld8(&g[8][6])  : ld8(&g[8][3]);
        const u64 Hi = odd ? ld8(&g[8][7])  : ld8(&g[8][4]);
        const u64 Hm = odd ? ld8(&g[8][8])  : ld8(&g[8][5]);
#pragma unroll
        for (int jj = 0; jj < 16; jj++) {
            const u64 pr = __shfl_xor_sync(0xFFFFFFFFu, cr[jj], 1);
            const u64 pi = __shfl_xor_sync(0xFFFFFFFFu, ci[jj], 1);
            const u64 nr = fma2(Hm, pi, fma2(Hr, pr, fma2(Gm, ci[jj], mul2(Gr, cr[jj]))));
            const u64 ni = fma2(Hr, pi, fma2(Hi, pr, fma2(Gr, ci[jj], mul2(Gi, cr[jj]))));
            cr[jj] = nr; ci[jj] = ni;
        }
    }

    // --- store ---
    if (PERM) {
        __syncthreads();  // in-place permuted store: all loads complete first
        const int sxb = slotf(sxf(base));
        const int pb  = __popc(base) & 1;   // base bit0 == 0
#pragma unroll
        for (int jj = 0; jj < 16; jj++) {
            const int K = ((jj & 1) << P0) | (((jj >> 1) & 1) << P1) |
                          (((jj >> 2) & 1) << P2) | (((jj >> 3) & 1) << P3);
            const int t = (sxb ^ slotf(sxf(K))) & ~1;
            const bool swap = (pb ^ parc(K)) != 0;
            u64 vr = cr[jj], vi = ci[jj];
            if (swap) {
                float a, b;
                unpk(vr, a, b); vr = pk(b, a);
                unpk(vi, a, b); vi = pk(b, a);
            }
            *reinterpret_cast<u64*>(&sre[t]) = vr;
            *reinterpret_cast<u64*>(&sim[t]) = vi;
        }
    } else {
#pragma unroll
        for (int jj = 0; jj < 16; jj++) {
            const int K = ((jj & 1) << P0) | (((jj >> 1) & 1) << P1) |
                          (((jj >> 2) & 1) << P2) | (((jj >> 3) & 1) << P3);
            const int a = sb ^ slotf(K);
            *reinterpret_cast<u64*>(&sre[a]) = cr[jj];
            *reinterpret_cast<u64*>(&sim[a]) = ci[jj];
        }
    }
    __syncthreads();
}

// ---------------------------------------------------------------------------
__global__ void __launch_bounds__(NT, 1)
qc_kernel(const float* __restrict__ x,
          const float* __restrict__ prx,
          const float* __restrict__ pry,
          const float* __restrict__ prz,
          const float* __restrict__ pent,
          float* __restrict__ out) {
    extern __shared__ float smem[];
    float* sre = smem;            // 16384 floats
    float* sim = smem + NSTATE;   // 16384 floats

    const int b    = blockIdx.x;
    const int tid  = threadIdx.x;
    const int lane = tid & 31;
    const int warp = tid >> 5;

    // ---- setup: coefficient tables, layers 1..3 (ent phases merged) --------
    if (tid < 42) {
        const int t = tid / NQ;
        const int i = tid % NQ;
        const int l = t + 1;
        float2 U[4];
        make_u(prx[l * NQ + i], pry[l * NQ + i], prz[l * NQ + i], U);
        if (i > 0) {
            float ce, se;
            sincosf(0.5f * pent[t * (NQ - 1) + (i - 1)], &se, &ce);
            float2 pe = { ce, -se };
            float2 qe = { ce,  se };
            U[0] = cmul(U[0], pe);
            U[2] = cmul(U[2], pe);
            U[1] = cmul(U[1], qe);
            U[3] = cmul(U[3], qe);
        }
        if (i == 13) {
            // special layout for in-register (pack-bit) gate
            gT[t][i][0] = make_float2( U[0].x,  U[3].x);  // A
            gT[t][i][1] = make_float2( U[1].x,  U[2].x);  // B
            gT[t][i][2] = make_float2( U[0].y,  U[3].y);  // E
            gT[t][i][3] = make_float2( U[1].y,  U[2].y);  // F
            gT[t][i][4] = make_float2(-U[0].y, -U[3].y);  // -E
            gT[t][i][5] = make_float2(-U[1].y, -U[2].y);  // -F
        } else {
#pragma unroll
            for (int r = 0; r < 4; r++) {
                gT[t][i][r * 3 + 0] = make_float2( U[r].x,  U[r].x);
                gT[t][i][r * 3 + 1] = make_float2( U[r].y,  U[r].y);
                gT[t][i][r * 3 + 2] = make_float2(-U[r].y, -U[r].y);
            }
        }
    }
    // ---- setup: per-sample product vectors (encoding RY + layer0) ----------
    if (tid >= 64 && tid < 64 + NQ) {
        const int i = tid - 64;
        float2 U[4];
        make_u(prx[i], pry[i], prz[i], U);
        const float enc = tanhf(x[b * NQ + i]) * PI_F;
        float ce, se;
        sincosf(0.5f * enc, &se, &ce);
        float2 a, c2;
        a.x  = U[0].x * ce + U[1].x * se;
        a.y  = U[0].y * ce + U[1].y * se;
        c2.x = U[2].x * ce + U[3].x * se;
        c2.y = U[2].y * ce + U[3].y * se;
        v0[i][0] = a;
        v0[i][1] = c2;
    }
    __syncthreads();

    // ---- init: product state with layer-0 entangle perm, paired layout -----
    // pair index m = (j<<9)|tid; amps w = 2m, 2m+1; z = gray(w).
    // z_p = m_{p-1} ^ m_p for p>=1 (indep of w0); z_0 = m_0 for lo, ^1 for hi.
    {
        float2 f = v0[12][( tid       ^ (tid >> 1)) & 1];
        f = cmul(f, v0[11][((tid >> 1) ^ (tid >> 2)) & 1]);
        f = cmul(f, v0[10][((tid >> 2) ^ (tid >> 3)) & 1]);
        f = cmul(f, v0[ 9][((tid >> 3) ^ (tid >> 4)) & 1]);
        f = cmul(f, v0[ 8][((tid >> 4) ^ (tid >> 5)) & 1]);
        f = cmul(f, v0[ 7][((tid >> 5) ^ (tid >> 6)) & 1]);
        f = cmul(f, v0[ 6][((tid >> 6) ^ (tid >> 7)) & 1]);
        f = cmul(f, v0[ 5][((tid >> 7) ^ (tid >> 8)) & 1]);
        const int mb = slotf(tid << 1);
        const int z0 = tid & 1;
#pragma unroll
        for (int j = 0; j < 16; j++) {
            float2 h = cmul(f, v0[4][((tid >> 8) ^ j) & 1]);        // p=9
            h = cmul(h, v0[3][( j       ^ (j >> 1)) & 1]);          // p=10
            h = cmul(h, v0[2][((j >> 1) ^ (j >> 2)) & 1]);          // p=11
            h = cmul(h, v0[1][((j >> 2) ^ (j >> 3)) & 1]);          // p=12
            h = cmul(h, v0[0][ (j >> 3)             & 1]);          // p=13
            const float2 alo = cmul(h, v0[13][z0]);
            const float2 ahi = cmul(h, v0[13][z0 ^ 1]);
            const int addr = mb ^ (j << 10);   // slotf(j<<10) == j<<10
            *reinterpret_cast<u64*>(&sre[addr]) = pk(alo.x, ahi.x);
            *reinterpret_cast<u64*>(&sim[addr]) = pk(alo.y, ahi.y);
        }
    }
    __syncthreads();

    // ---- layers 1..3: 3 passes each ----------------------------------------
#pragma unroll 1
    for (int t = 0; t < 3; t++) {
        const float2 (*g)[12] = gT[t];
        // A: jj gates {6,7,8,9} (qubits 7,6,5,4) + reg gate qubit 13
        pass<6, 7, 8, 9,   1, 2, 3, 4, 5,   10, 11, 12, 13,
             true, false, false>(sre, sim, g, lane, warp);
        // B: jj gates {1,2,3,4} (qubits 12,11,10,9) + shfl gate qubit 8
        pass<1, 2, 3, 4,   5, 6, 7, 8, 9,   10, 11, 12, 13,
             false, true, false>(sre, sim, g, lane, warp);
        // C: jj gates {10,11,12,13} (qubits 3,2,1,0) + entangle perm store
        pass<10, 11, 12, 13,   1, 2, 3, 4, 5,   6, 7, 8, 9,
             false, false, true>(sre, sim, g, lane, warp);
    }

    // ---- measurement: state in final index basis, paired layout ------------
    // pair m = (j<<9)|tid; lo half = qubit13=0, hi half = qubit13=1.
    // m bit b (b=0..8: tid; b=9..12: j) <-> qubit 12-b.
    u64 tacc = 0, q0a = 0, q1a = 0, q2a = 0, q3a = 0;
    {
        const int mb = slotf(tid << 1);
#pragma unroll
        for (int j = 0; j < 16; j++) {
            const int addr = mb ^ (j << 10);
            const u64 ar = *reinterpret_cast<const u64*>(&sre[addr]);
            const u64 ai = *reinterpret_cast<const u64*>(&sim[addr]);
            const u64 p2 = fma2(ai, ai, mul2(ar, ar));
            tacc = add2(tacc, p2);
            if (j & 1) q3a = add2(q3a, p2);   // m bit 9  -> qubit 3
            if (j & 2) q2a = add2(q2a, p2);
            if (j & 4) q1a = add2(q1a, p2);
            if (j & 8) q0a = add2(q0a, p2);   // m bit 12 -> qubit 0
        }
    }
    float s[NQ], tsum;
    {
        float tl, th;
        unpk(tacc, tl, th);
        tsum = tl + th;
        s[13] = th;                 // hi halves = qubit13 bit set
        float a2, b2;
        unpk(q0a, a2, b2); s[0] = a2 + b2;
        unpk(q1a, a2, b2); s[1] = a2 + b2;
        unpk(q2a, a2, b2); s[2] = a2 + b2;
        unpk(q3a, a2, b2); s[3] = a2 + b2;
#pragma unroll
        for (int q = 4; q < 13; q++)
            s[q] = ((tid >> (12 - q)) & 1) ? tsum : 0.f;
    }

#pragma unroll
    for (int o = 16; o; o >>= 1) {
        tsum += __shfl_xor_sync(0xFFFFFFFFu, tsum, o);
#pragma unroll
        for (int q = 0; q < NQ; q++)
            s[q] += __shfl_xor_sync(0xFFFFFFFFu, s[q], o);
    }
    if (lane == 0) {
        red[warp][0] = tsum;
#pragma unroll
        for (int q = 0; q < NQ; q++) red[warp][1 + q] = s[q];
    }
    __syncthreads();

    if (tid < NQ) {
        float tt = 0.f, ss = 0.f;
#pragma unroll
        for (int w = 0; w < 16; w++) {
            tt += red[w][0];
            ss += red[w][1 + tid];
        }
        out[b * NQ + tid] = tt - 2.f * ss;
    }
}

// ---------------------------------------------------------------------------
extern "C" void kernel_launch(void* const* d_in, const int* in_sizes, int n_in,
                              void* d_out, int out_size) {
    const float* x    = (const float*)d_in[0];
    const float* prx  = (const float*)d_in[1];
    const float* pry  = (const float*)d_in[2];
    const float* prz  = (const float*)d_in[3];
    const float* pent = (const float*)d_in[4];
    float* out = (float*)d_out;

    const int B = in_sizes[0] / NQ;
    const size_t smem = 2 * NSTATE * sizeof(float);  // 131072 bytes SoA

    cudaFuncSetAttribute(qc_kernel,
                         cudaFuncAttributeMaxDynamicSharedMemorySize,
                         (int)smem);
    qc_kernel<<<B, NT, smem>>>(x, prx, pry, prz, pent, out);
}